// round 1
// baseline (speedup 1.0000x reference)
#include <cuda_runtime.h>
#include <cstdint>

// Tile config
#define BM 128   // spatial tile
#define BN 64    // output-channel tile (255 total -> 4 tiles)
#define BK 32    // k tile
#define NTHREADS 256

__device__ __forceinline__ uint32_t f2tf32(float x) {
    uint32_t r;
    asm("cvt.rna.tf32.f32 %0, %1;" : "=r"(r) : "f"(x));
    return r;
}

__device__ __forceinline__ void mma_tf32(float d[4], const uint32_t a[4],
                                         const uint32_t b[2], const float c[4]) {
    asm volatile(
        "mma.sync.aligned.m16n8k8.row.col.f32.tf32.tf32.f32 "
        "{%0,%1,%2,%3}, {%4,%5,%6,%7}, {%8,%9}, {%10,%11,%12,%13};"
        : "=f"(d[0]), "=f"(d[1]), "=f"(d[2]), "=f"(d[3])
        : "r"(a[0]), "r"(a[1]), "r"(a[2]), "r"(a[3]),
          "r"(b[0]), "r"(b[1]),
          "f"(c[0]), "f"(c[1]), "f"(c[2]), "f"(c[3]));
}

// One scale: Y[m, n] = sum_k X[k, m] * W[n, k]  (per batch b)
//   X = p[b]  : [K, S], m-contiguous
//   W         : [255, K] row-major
// Epilogue: sigmoid + YOLO decode, write to out[b, base + a*S + m, no]
__global__ __launch_bounds__(NTHREADS, 2)
void yolo_fused_gemm(const float* __restrict__ p,
                     const float* __restrict__ w,
                     const float* __restrict__ bias,
                     const float* __restrict__ anchors,  // pre-offset to scale: [3][2]
                     float* __restrict__ out,
                     int K, int S, int nx, float stride, int scale_base) {
    __shared__ uint32_t Xs[BK][BM + 4];   // tf32 bits, padded (bank-conflict-free frags)
    __shared__ uint32_t Ws[BN][BK + 4];
    __shared__ float sbias[BN];

    const int tid = threadIdx.x;
    const int b   = blockIdx.z;
    const int m0  = blockIdx.x * BM;
    const int n0  = blockIdx.y * BN;

    const float* __restrict__ pb = p + (size_t)b * K * S;

    if (tid < BN) {
        int n = n0 + tid;
        sbias[tid] = (n < 255) ? bias[n] : 0.0f;
    }

    // ---- global loader thread mapping ----
    // X: 32 (k) x 128 (m) floats = 1024 float4; 4 per thread
    const int xm = (tid & 31) * 4;          // m offset (float4)
    const int xk = tid >> 5;                // k row base (rows xk + 8*i)
    const bool xvalid = (m0 + xm) < S;      // S % 4 == 0, m0 % 128 == 0
    // W: 64 (n) x 32 (k) floats = 512 float4; 2 per thread
    const int wn = tid >> 3;                // n row base (rows wn + 32*i)
    const int wk = (tid & 7) * 4;           // k offset (float4)

    float4 xr[4];
    float4 wr[2];

    const float4 zero4 = make_float4(0.f, 0.f, 0.f, 0.f);

    // warp/lane decomposition for MMA
    const int lane = tid & 31;
    const int wid  = tid >> 5;
    const int warp_m = wid & 3;   // 0..3
    const int warp_n = wid >> 2;  // 0..1
    const int gid = lane >> 2;    // 0..7
    const int tig = lane & 3;     // 0..3

    float acc[2][4][4];
#pragma unroll
    for (int mi = 0; mi < 2; ++mi)
#pragma unroll
        for (int ni = 0; ni < 4; ++ni)
#pragma unroll
            for (int r = 0; r < 4; ++r) acc[mi][ni][r] = 0.f;

    // prefetch k0 = 0
    {
#pragma unroll
        for (int i = 0; i < 4; ++i) {
            xr[i] = xvalid ? *(const float4*)(pb + (size_t)(xk + 8 * i) * S + m0 + xm)
                           : zero4;
        }
#pragma unroll
        for (int i = 0; i < 2; ++i) {
            int n = n0 + wn + 32 * i;
            wr[i] = (n < 255) ? *(const float4*)(w + (size_t)n * K + wk) : zero4;
        }
    }

    for (int k0 = 0; k0 < K; k0 += BK) {
        __syncthreads();
        // store staged tile (convert to tf32 bits once here)
#pragma unroll
        for (int i = 0; i < 4; ++i) {
            uint32_t* dst = &Xs[xk + 8 * i][xm];
            dst[0] = f2tf32(xr[i].x);
            dst[1] = f2tf32(xr[i].y);
            dst[2] = f2tf32(xr[i].z);
            dst[3] = f2tf32(xr[i].w);
        }
#pragma unroll
        for (int i = 0; i < 2; ++i) {
            uint32_t* dst = &Ws[wn + 32 * i][wk];
            dst[0] = f2tf32(wr[i].x);
            dst[1] = f2tf32(wr[i].y);
            dst[2] = f2tf32(wr[i].z);
            dst[3] = f2tf32(wr[i].w);
        }
        __syncthreads();

        // issue next tile's global loads (latency hides behind MMAs)
        const int kn = k0 + BK;
        if (kn < K) {
#pragma unroll
            for (int i = 0; i < 4; ++i) {
                xr[i] = xvalid
                    ? *(const float4*)(pb + (size_t)(kn + xk + 8 * i) * S + m0 + xm)
                    : zero4;
            }
#pragma unroll
            for (int i = 0; i < 2; ++i) {
                int n = n0 + wn + 32 * i;
                wr[i] = (n < 255) ? *(const float4*)(w + (size_t)n * K + kn + wk)
                                  : zero4;
            }
        }

        // MMA over the tile
#pragma unroll
        for (int kk = 0; kk < BK; kk += 8) {
            uint32_t af[2][4];
            uint32_t bf[4][2];
#pragma unroll
            for (int mi = 0; mi < 2; ++mi) {
                const int mb = warp_m * 32 + mi * 16;
                af[mi][0] = Xs[kk + tig][mb + gid];
                af[mi][1] = Xs[kk + tig][mb + gid + 8];
                af[mi][2] = Xs[kk + tig + 4][mb + gid];
                af[mi][3] = Xs[kk + tig + 4][mb + gid + 8];
            }
#pragma unroll
            for (int ni = 0; ni < 4; ++ni) {
                const int nb = warp_n * 32 + ni * 8;
                bf[ni][0] = Ws[nb + gid][kk + tig];
                bf[ni][1] = Ws[nb + gid][kk + tig + 4];
            }
#pragma unroll
            for (int mi = 0; mi < 2; ++mi)
#pragma unroll
                for (int ni = 0; ni < 4; ++ni)
                    mma_tf32(acc[mi][ni], af[mi], bf[ni], acc[mi][ni]);
        }
    }

    // ---- fused epilogue: bias + sigmoid + decode + store ----
    const size_t out_batch = (size_t)b * 25200 + scale_base;
#pragma unroll
    for (int mi = 0; mi < 2; ++mi) {
#pragma unroll
        for (int ni = 0; ni < 4; ++ni) {
            const int mrow0 = m0 + warp_m * 32 + mi * 16 + gid;
            const int ncol0 = n0 + warp_n * 32 + ni * 8 + tig * 2;
#pragma unroll
            for (int r = 0; r < 4; ++r) {
                const int m = mrow0 + ((r >= 2) ? 8 : 0);
                const int n = ncol0 + (r & 1);
                if (m < S && n < 255) {
                    const float v = acc[mi][ni][r] + sbias[n - n0];
                    const float sg = 1.0f / (1.0f + __expf(-v));
                    const int a  = n / 85;
                    const int no = n - a * 85;
                    float ov;
                    if (no == 0) {
                        const int x = m % nx;
                        ov = (2.0f * sg + (float)x - 0.5f) * stride;
                    } else if (no == 1) {
                        const int y = m / nx;
                        ov = (2.0f * sg + (float)y - 0.5f) * stride;
                    } else if (no < 4) {
                        const float t = 2.0f * sg;
                        ov = t * t * __ldg(anchors + a * 2 + (no - 2));
                    } else {
                        ov = sg;
                    }
                    out[(out_batch + (size_t)a * S + m) * 85 + no] = ov;
                }
            }
        }
    }
}

extern "C" void kernel_launch(void* const* d_in, const int* in_sizes, int n_in,
                              void* d_out, int out_size) {
    const float* p0 = (const float*)d_in[0];
    const float* p1 = (const float*)d_in[1];
    const float* p2 = (const float*)d_in[2];
    const float* w0 = (const float*)d_in[3];
    const float* b0 = (const float*)d_in[4];
    const float* w1 = (const float*)d_in[5];
    const float* b1 = (const float*)d_in[6];
    const float* w2 = (const float*)d_in[7];
    const float* b2 = (const float*)d_in[8];
    const float* anc = (const float*)d_in[9];
    float* out = (float*)d_out;

    dim3 blk(NTHREADS);
    // scale 0: K=256, S=6400 (80x80), stride 8, base 0
    yolo_fused_gemm<<<dim3((6400 + BM - 1) / BM, 4, 16), blk>>>(
        p0, w0, b0, anc + 0, out, 256, 6400, 80, 8.0f, 0);
    // scale 1: K=512, S=1600 (40x40), stride 16, base 3*6400=19200
    yolo_fused_gemm<<<dim3((1600 + BM - 1) / BM, 4, 16), blk>>>(
        p1, w1, b1, anc + 6, out, 512, 1600, 40, 16.0f, 19200);
    // scale 2: K=1024, S=400 (20x20), stride 32, base 19200+3*1600=24000
    yolo_fused_gemm<<<dim3((400 + BM - 1) / BM, 4, 16), blk>>>(
        p2, w2, b2, anc + 12, out, 1024, 400, 20, 32.0f, 24000);
}

// round 4
// speedup vs baseline: 1.7127x; 1.7127x over previous
#include <cuda_runtime.h>
#include <cstdint>

#define NT 256

// Pre-swizzled, tf32-rounded, truncation-compensated weights.
// Layout per scale, per n-tile(64ch), per kkb(8k), image of A-fragments:
//   idx = (((kkb*4+cg)*4+gh)*2+gl)*16 + t*4 + i
//   i=0:(ch=cg*16+g,    k=kkb*8+t)   i=1:(ch+8, k)
//   i=2:(ch,            k+4)         i=3:(ch+8, k+4)      with g = gh*2+gl
// sizes: K*256 floats per scale -> 65536 + 131072 + 262144 = 458752
__device__ float g_wswz[458752];

__device__ __forceinline__ void cp16(uint32_t dst, const float* src, bool pred) {
    asm volatile("cp.async.cg.shared.global [%0], [%1], 16, %2;\n"
                 :: "r"(dst), "l"(__cvta_generic_to_global(src)),
                    "r"(pred ? 16 : 0));
}

__device__ __forceinline__ void mma_tf32(float d[4], const uint32_t a[4],
                                         const uint32_t b[2], const float c[4]) {
    asm volatile(
        "mma.sync.aligned.m16n8k8.row.col.f32.tf32.tf32.f32 "
        "{%0,%1,%2,%3}, {%4,%5,%6,%7}, {%8,%9}, {%10,%11,%12,%13};"
        : "=f"(d[0]), "=f"(d[1]), "=f"(d[2]), "=f"(d[3])
        : "r"(a[0]), "r"(a[1]), "r"(a[2]), "r"(a[3]),
          "r"(b[0]), "r"(b[1]),
          "f"(c[0]), "f"(c[1]), "f"(c[2]), "f"(c[3]));
}

// ---------------- W prep: rna-tf32 + compensation + fragment swizzle ----------
__global__ void yolo_prep(const float* __restrict__ w0,
                          const float* __restrict__ w1,
                          const float* __restrict__ w2) {
    int idx = blockIdx.x * NT + threadIdx.x;
    if (idx >= 458752) return;
    const float* w; int K, base;
    if (idx < 65536)       { w = w0; K = 256;  base = 0; }
    else if (idx < 196608) { w = w1; K = 512;  base = 65536; }
    else                   { w = w2; K = 1024; base = 196608; }
    int r = idx - base;
    int nt = r / (K * 64); r -= nt * (K * 64);
    int kkb = r >> 9;  r &= 511;
    int cg  = r >> 7;  r &= 127;
    int gh  = r >> 5;  r &= 31;
    int gl  = r >> 4;  r &= 15;
    int t   = r >> 2;  int i = r & 3;
    int g = gh * 2 + gl;
    int n = nt * 64 + cg * 16 + g + (i & 1) * 8;
    int k = kkb * 8 + t + (i >> 1) * 4;
    float v = 0.f;
    if (n < 255) {
        // compensate the mean X-truncation shrink (E[rel] ~= 2^-11 * ln2-ish)
        float x = w[n * K + k] * 1.000352f;
        uint32_t u;
        asm("cvt.rna.tf32.f32 %0, %1;" : "=r"(u) : "f"(x));
        v = __uint_as_float(u);
    }
    g_wswz[idx] = v;
}

// ---------------- fused main: 3 scales, GEMM + decode ------------------------
// CTA tile: 64 channels x 128 spatial, BK=32. 8 warps = 2(ch) x 4(sp),
// warp tile 32ch x 32sp. MMA: A=W (m16 = channels), B=X (n8 = spatial).
__global__ __launch_bounds__(NT, 3)
void yolo_main(const float* __restrict__ p0, const float* __restrict__ p1,
               const float* __restrict__ p2,
               const float* __restrict__ bb0, const float* __restrict__ bb1,
               const float* __restrict__ bb2,
               const float* __restrict__ anchors, float* __restrict__ out) {
    extern __shared__ float smem[];   // 2 stages x (X 32x136 + W 2048) floats
    __shared__ float sbias[64];

    const int tid = threadIdx.x;
    const int bx  = blockIdx.x;
    const int nt  = blockIdx.y;
    const int b   = blockIdx.z;

    const float* p; const float* bias; const float* anc;
    int K, S, nx, sh, mt, sbase, woff; float strd;
    if (bx < 50)      { p=p0; bias=bb0; anc=anchors;      K=256;  S=6400; nx=80; sh=6; mt=bx;    sbase=0;     woff=0;      strd=8.f;  }
    else if (bx < 63) { p=p1; bias=bb1; anc=anchors+6;    K=512;  S=1600; nx=40; sh=5; mt=bx-50; sbase=19200; woff=65536;  strd=16.f; }
    else              { p=p2; bias=bb2; anc=anchors+12;   K=1024; S=400;  nx=20; sh=4; mt=bx-63; sbase=24000; woff=196608; strd=32.f; }

    const int m0 = mt * 128;
    const int n0 = nt * 64;

    if (tid < 64) sbias[tid] = (n0 + tid < 255) ? bias[n0 + tid] : 0.f;

    // ---- async loaders ----
    const int  xm = (tid & 31) * 4;        // spatial (4 floats)
    const int  xk = tid >> 5;              // k row base (rows xk+8i)
    const bool xv = (m0 + xm) < S;
    const float* xg = p + (size_t)b * K * S + (size_t)xk * S + (m0 + xm);
    const float* wg = g_wswz + woff + nt * (K * 64) + tid * 8;

    const uint32_t sb = (uint32_t)__cvta_generic_to_shared(smem);
    const int nk = K >> 5;

    auto issue = [&](int tt, int ss) {
        const float* xs = xg + (size_t)(tt << 5) * S;
        const uint32_t xb = sb + (uint32_t)(ss * 6400 + xm) * 4u;
#pragma unroll
        for (int i = 0; i < 4; ++i)
            cp16(xb + (uint32_t)((xk + 8 * i) * 136) * 4u,
                 xs + (size_t)(8 * i) * S, xv);
        const float* ws = wg + tt * 2048;
        const uint32_t wb = sb + (uint32_t)(ss * 6400 + 4352 + tid * 8) * 4u;
        cp16(wb,      ws,     true);
        cp16(wb + 16, ws + 4, true);
        asm volatile("cp.async.commit_group;\n");
    };

    const int lane = tid & 31, wid = tid >> 5;
    const int c  = wid >> 2;   // channel half (0..1)
    const int sp = wid & 3;    // spatial quarter (0..3)
    const int g  = lane >> 2, tg = lane & 3;

    float acc[2][4][4];
#pragma unroll
    for (int mi = 0; mi < 2; ++mi)
#pragma unroll
        for (int ni = 0; ni < 4; ++ni)
#pragma unroll
            for (int r = 0; r < 4; ++r) acc[mi][ni][r] = 0.f;

    issue(0, 0);

    for (int t = 0; t < nk; ++t) {
        if (t + 1 < nk) {
            issue(t + 1, (t + 1) & 1);
            asm volatile("cp.async.wait_group 1;\n");
        } else {
            asm volatile("cp.async.wait_group 0;\n");
        }
        __syncthreads();

        const float* st = smem + (t & 1) * 6400;
        const uint32_t* Xs = (const uint32_t*)st;
        const uint32_t* Ws = (const uint32_t*)(st + 4352);

#pragma unroll
        for (int kkb = 0; kkb < 4; ++kkb) {
            uint32_t af[2][4];
#pragma unroll
            for (int mi = 0; mi < 2; ++mi) {
                uint4 v = *(const uint4*)(Ws + kkb * 512 + (c * 2 + mi) * 128 +
                                          (g >> 1) * 32 + (g & 1) * 16 + tg * 4);
                af[mi][0] = v.x; af[mi][1] = v.y; af[mi][2] = v.z; af[mi][3] = v.w;
            }
            uint32_t bf[4][2];
#pragma unroll
            for (int ni = 0; ni < 4; ++ni) {
                const int mcol = sp * 32 + ni * 8 + g;
                bf[ni][0] = Xs[(kkb * 8 + tg) * 136 + mcol];
                bf[ni][1] = Xs[(kkb * 8 + tg + 4) * 136 + mcol];
            }
#pragma unroll
            for (int mi = 0; mi < 2; ++mi)
#pragma unroll
                for (int ni = 0; ni < 4; ++ni)
                    mma_tf32(acc[mi][ni], af[mi], bf[ni], acc[mi][ni]);
        }
        __syncthreads();
    }

    // ---- fused epilogue: bias + sigmoid + YOLO decode ----
    const size_t ob = (size_t)b * 25200 + sbase;
#pragma unroll
    for (int mi = 0; mi < 2; ++mi)
#pragma unroll
        for (int ni = 0; ni < 4; ++ni)
#pragma unroll
            for (int r = 0; r < 4; ++r) {
                const int n = n0 + c * 32 + mi * 16 + g + ((r & 2) ? 8 : 0);
                const int m = m0 + sp * 32 + ni * 8 + tg * 2 + (r & 1);
                if (n < 255 && m < S) {
                    const float v  = acc[mi][ni][r] + sbias[n - n0];
                    const float sg = 1.f / (1.f + __expf(-v));
                    const int a  = (n * 772) >> 16;   // n / 85 for n < 255
                    const int no = n - a * 85;
                    float ov;
                    if (no < 2) {
                        const int y = (int)(__umulhi((unsigned)m, 3435973837u) >> sh);
                        const int gcoord = (no == 0) ? (m - y * nx) : y;
                        ov = (2.f * sg + (float)gcoord - 0.5f) * strd;
                    } else if (no < 4) {
                        const float tt2 = 2.f * sg;
                        ov = tt2 * tt2 * __ldg(anc + a * 2 + (no - 2));
                    } else {
                        ov = sg;
                    }
                    out[(ob + (size_t)a * S + m) * 85 + no] = ov;
                }
            }
}

extern "C" void kernel_launch(void* const* d_in, const int* in_sizes, int n_in,
                              void* d_out, int out_size) {
    const float* p0 = (const float*)d_in[0];
    const float* p1 = (const float*)d_in[1];
    const float* p2 = (const float*)d_in[2];
    const float* w0 = (const float*)d_in[3];
    const float* b0 = (const float*)d_in[4];
    const float* w1 = (const float*)d_in[5];
    const float* b1 = (const float*)d_in[6];
    const float* w2 = (const float*)d_in[7];
    const float* b2 = (const float*)d_in[8];
    const float* anc = (const float*)d_in[9];
    float* out = (float*)d_out;

    cudaFuncSetAttribute(yolo_main, cudaFuncAttributeMaxDynamicSharedMemorySize,
                         51200);

    yolo_prep<<<1792, NT>>>(w0, w1, w2);
    // m-tiles: 50 (80x80) + 13 (40x40) + 4 (20x20) = 67
    yolo_main<<<dim3(67, 4, 16), NT, 51200>>>(p0, p1, p2, b0, b1, b2, anc, out);
}